// round 15
// baseline (speedup 1.0000x reference)
#include <cuda_runtime.h>
#include <math.h>

// Problem constants
#define NN    512
#define CS    384
#define CZ    128
#define HH    12
#define CH    16
#define PQN   4
#define PVN   8
#define DPROJ 1152
#define FH    (CH + PVN*3 + PVN + CZ)  // 176
#define FEAT  (HH*FH)                  // 2112
#define COUT  384
#define DK    28                       // combined qk+point dim

// segment bases inside g_proj row
#define OFF_PQ_Q   0
#define OFF_PQ_K   192
#define OFF_PQ_V   384
#define OFF_PQ_QP  576
#define OFF_PQ_KP  720
#define OFF_PQ_VP  864

// ---------------- scratch ----------------
__device__ __align__(16) float g_proj[NN*DPROJ];
__device__ __align__(16) float g_qk  [HH*NN*DK];            // Q' = [0.25*q, qpg]
__device__ __align__(16) float g_kk  [HH*NN*DK];            // K' = [k, kpg]
__device__ __align__(16) float g_sqk [HH*NN];               // 0.5*|kpg|^2
__device__ __align__(16) float g_v40 [(size_t)HH*NN*40];    // [h][n][v(16)|vpg(24)]
__device__ __align__(16) float g_feat[NN*FEAT];
__device__ __align__(16) float g_zb  [(size_t)HH*NN*NN];    // [h][n][m]
__device__ __align__(16) float g_att [(size_t)HH*NN*NN];    // logits -> weights
#define SPLITS 6
__device__ __align__(16) float g_opart[SPLITS][NN][COUT];

// =================== fused projection SGEMM ===========================
#define PT_M 64
#define PT_N 48
#define PT_K 16
__global__ void proj_gemm_kernel(const float* __restrict__ s,
    const float* __restrict__ wq,  const float* __restrict__ bq,
    const float* __restrict__ wk,  const float* __restrict__ bk,
    const float* __restrict__ wv,  const float* __restrict__ bv,
    const float* __restrict__ wqp, const float* __restrict__ bqp,
    const float* __restrict__ wkp, const float* __restrict__ bkp,
    const float* __restrict__ wvp, const float* __restrict__ bvp) {
    int bt = blockIdx.y;
    const float *W, *B; int Dout, base, t;
    if      (bt < 4)  { W=wq;  B=bq;  Dout=192; base=OFF_PQ_Q;  t=bt; }
    else if (bt < 8)  { W=wk;  B=bk;  Dout=192; base=OFF_PQ_K;  t=bt-4; }
    else if (bt < 12) { W=wv;  B=bv;  Dout=192; base=OFF_PQ_V;  t=bt-8; }
    else if (bt < 15) { W=wqp; B=bqp; Dout=144; base=OFF_PQ_QP; t=bt-12; }
    else if (bt < 18) { W=wkp; B=bkp; Dout=144; base=OFF_PQ_KP; t=bt-15; }
    else              { W=wvp; B=bvp; Dout=288; base=OFF_PQ_VP; t=bt-18; }
    int col0 = t*PT_N;
    int n0   = blockIdx.x*PT_M;

    __shared__ float sA[PT_K][PT_M];
    __shared__ float sB[PT_K][PT_N];
    int tid = threadIdx.x;           // 192
    int tx = tid % 12, ty = tid / 12;
    float4 acc[4] = {};

    for (int k0 = 0; k0 < CS; k0 += PT_K) {
        for (int i = tid; i < PT_M*PT_K/4; i += 192) {
            int m = i >> 2, k4 = (i & 3) * 4;
            float4 v = *(const float4*)(s + (size_t)(n0+m)*CS + k0 + k4);
            sA[k4+0][m]=v.x; sA[k4+1][m]=v.y; sA[k4+2][m]=v.z; sA[k4+3][m]=v.w;
        }
        for (int i = tid; i < PT_K*PT_N/4; i += 192) {
            int k = i / 12, c4 = (i % 12) * 4;
            *(float4*)&sB[k][c4] = *(const float4*)(W + (size_t)(k0+k)*Dout + col0 + c4);
        }
        __syncthreads();
        #pragma unroll
        for (int kk = 0; kk < PT_K; kk++) {
            float4 b = *(float4*)&sB[kk][tx*4];
            float4 a = *(float4*)&sA[kk][ty*4];
            acc[0].x += a.x*b.x; acc[0].y += a.x*b.y; acc[0].z += a.x*b.z; acc[0].w += a.x*b.w;
            acc[1].x += a.y*b.x; acc[1].y += a.y*b.y; acc[1].z += a.y*b.z; acc[1].w += a.y*b.w;
            acc[2].x += a.z*b.x; acc[2].y += a.z*b.y; acc[2].z += a.z*b.z; acc[2].w += a.z*b.w;
            acc[3].x += a.w*b.x; acc[3].y += a.w*b.y; acc[3].z += a.w*b.z; acc[3].w += a.w*b.w;
        }
        __syncthreads();
    }
    float4 bias4 = *(const float4*)(B + col0 + tx*4);
    #pragma unroll
    for (int r = 0; r < 4; r++) {
        float4 o = acc[r];
        o.x += bias4.x; o.y += bias4.y; o.z += bias4.z; o.w += bias4.w;
        *(float4*)(g_proj + (size_t)(n0+ty*4+r)*DPROJ + base + col0 + tx*4) = o;
    }
}

// =================== prep: rotate points, build Q'/K'/sqk/v40 =========
__global__ void prep_kernel(const float* __restrict__ rot,
                            const float* __restrict__ trans) {
    int n = blockIdx.x, t = threadIdx.x;   // 192 threads
    __shared__ float R[9], T[3];
    __shared__ float kpg_s[144];
    if (t < 9) R[t] = rot[n*9 + t];
    if (t < 3) T[t] = trans[n*3 + t];
    __syncthreads();

    {
        int h = t / 16, c = t % 16;
        g_qk[(size_t)h*NN*DK + n*DK + c] = g_proj[(size_t)n*DPROJ + t] * 0.25f;
        g_kk[(size_t)h*NN*DK + n*DK + c] = g_proj[(size_t)n*DPROJ + 192 + t];
        // pack v scalar part into v40
        g_v40[(size_t)h*NN*40 + (size_t)n*40 + c] =
            g_proj[(size_t)n*DPROJ + OFF_PQ_V + t];
    }
    if (t < 48) {               // qp
        const float* l = g_proj + (size_t)n*DPROJ + OFF_PQ_QP + t*3;
        float l0=l[0], l1=l[1], l2=l[2];
        int h = t/4, p = t%4;
        float* dst = g_qk + (size_t)h*NN*DK + n*DK + 16 + p*3;
        dst[0] = R[0]*l0 + R[1]*l1 + R[2]*l2 + T[0];
        dst[1] = R[3]*l0 + R[4]*l1 + R[5]*l2 + T[1];
        dst[2] = R[6]*l0 + R[7]*l1 + R[8]*l2 + T[2];
    } else if (t < 96) {        // kp
        int tt = t - 48;
        const float* l = g_proj + (size_t)n*DPROJ + OFF_PQ_KP + tt*3;
        float l0=l[0], l1=l[1], l2=l[2];
        int h = tt/4, p = tt%4;
        float g0 = R[0]*l0 + R[1]*l1 + R[2]*l2 + T[0];
        float g1 = R[3]*l0 + R[4]*l1 + R[5]*l2 + T[1];
        float g2 = R[6]*l0 + R[7]*l1 + R[8]*l2 + T[2];
        float* dst = g_kk + (size_t)h*NN*DK + n*DK + 16 + p*3;
        dst[0]=g0; dst[1]=g1; dst[2]=g2;
        kpg_s[tt*3+0]=g0; kpg_s[tt*3+1]=g1; kpg_s[tt*3+2]=g2;
    } else {                    // vp -> packed into v40 cols 16..39
        int tt = t - 96;        // 0..95 = h*8+p
        const float* l = g_proj + (size_t)n*DPROJ + OFF_PQ_VP + tt*3;
        float l0=l[0], l1=l[1], l2=l[2];
        int h = tt/8, p = tt%8;
        float* dst = g_v40 + (size_t)h*NN*40 + (size_t)n*40 + 16 + p*3;
        dst[0] = R[0]*l0 + R[1]*l1 + R[2]*l2 + T[0];
        dst[1] = R[3]*l0 + R[4]*l1 + R[5]*l2 + T[1];
        dst[2] = R[6]*l0 + R[7]*l1 + R[8]*l2 + T[2];
    }
    __syncthreads();
    if (t < HH) {
        float s = 0.f;
        #pragma unroll
        for (int j = 0; j < 12; j++) { float v = kpg_s[t*12 + j]; s += v*v; }
        g_sqk[t*NN + n] = 0.5f * s;
    }
}

// =================== zb GEMM: smem-staged, one block per n ============
#define ZKC 16
__global__ void zb_gemm_kernel(const float* __restrict__ z,
                               const float* __restrict__ wb) {
    __shared__ float z_s[NN*(ZKC+1)];
    __shared__ float wb_s[CZ*HH];
    int n = blockIdx.x, tid = threadIdx.x;   // 128
    for (int i = tid; i < CZ*HH; i += 128) wb_s[i] = wb[i];

    float acc[4][HH] = {};
    const float* zrow = z + (size_t)n*NN*CZ;

    for (int c = 0; c < CZ/ZKC; c++) {
        __syncthreads();
        for (int i = tid; i < NN*ZKC/4; i += 128) {
            int row = i >> 2, c4 = (i & 3) * 4;
            float4 v = *(const float4*)(zrow + (size_t)row*CZ + c*ZKC + c4);
            float* d = z_s + row*(ZKC+1) + c4;
            d[0]=v.x; d[1]=v.y; d[2]=v.z; d[3]=v.w;
        }
        __syncthreads();
        #pragma unroll
        for (int k = 0; k < ZKC; k++) {
            const float* wrow = wb_s + (c*ZKC + k)*HH;
            float zv[4];
            #pragma unroll
            for (int r = 0; r < 4; r++) zv[r] = z_s[(tid + 128*r)*(ZKC+1) + k];
            #pragma unroll
            for (int h = 0; h < HH; h++) {
                float w = wrow[h];
                acc[0][h] += zv[0]*w;
                acc[1][h] += zv[1]*w;
                acc[2][h] += zv[2]*w;
                acc[3][h] += zv[3]*w;
            }
        }
    }
    #pragma unroll
    for (int h = 0; h < HH; h++) {
        float* dst = g_zb + (size_t)h*NN*NN + (size_t)n*NN;
        #pragma unroll
        for (int r = 0; r < 4; r++) dst[tid + 128*r] = acc[r][h];
    }
}

// =================== logits GEMM: per-head 64x64x28 + epilogue ========
__global__ void logits_gemm_kernel(const int* __restrict__ mask) {
    int m0 = blockIdx.x*64, n0 = blockIdx.y*64, h = blockIdx.z;
    __shared__ float Qs[DK][64];
    __shared__ float Ks[DK][64];
    int tid = threadIdx.x;   // 256
    int tx = tid & 15, ty = tid >> 4;

    const float4* qsrc = (const float4*)(g_qk + (size_t)h*NN*DK + (size_t)n0*DK);
    const float4* ksrc = (const float4*)(g_kk + (size_t)h*NN*DK + (size_t)m0*DK);
    for (int i = tid; i < 64*7; i += 256) {
        int row = i / 7, q = i % 7;
        float4 v = qsrc[row*7 + q];
        Qs[q*4+0][row]=v.x; Qs[q*4+1][row]=v.y; Qs[q*4+2][row]=v.z; Qs[q*4+3][row]=v.w;
        float4 w = ksrc[row*7 + q];
        Ks[q*4+0][row]=w.x; Ks[q*4+1][row]=w.y; Ks[q*4+2][row]=w.z; Ks[q*4+3][row]=w.w;
    }
    __syncthreads();

    float4 acc[4] = {};
    #pragma unroll
    for (int k = 0; k < DK; k++) {
        float4 b = *(float4*)&Ks[k][tx*4];
        float4 a = *(float4*)&Qs[k][ty*4];
        acc[0].x += a.x*b.x; acc[0].y += a.x*b.y; acc[0].z += a.x*b.z; acc[0].w += a.x*b.w;
        acc[1].x += a.y*b.x; acc[1].y += a.y*b.y; acc[1].z += a.y*b.z; acc[1].w += a.y*b.w;
        acc[2].x += a.z*b.x; acc[2].y += a.z*b.y; acc[2].z += a.z*b.z; acc[2].w += a.z*b.w;
        acc[3].x += a.w*b.x; acc[3].y += a.w*b.y; acc[3].z += a.w*b.z; acc[3].w += a.w*b.w;
    }

    float4 sq = *(const float4*)(g_sqk + h*NN + m0 + tx*4);
    int4 mm = *(const int4*)(mask + m0 + tx*4);
    #pragma unroll
    for (int r = 0; r < 4; r++) {
        int row = n0 + ty*4 + r;
        int mn = __ldg(mask + row);
        float4 zbv = *(const float4*)(g_zb + (size_t)h*NN*NN + (size_t)row*NN + m0 + tx*4);
        float4 o;
        o.x = acc[r].x + zbv.x - sq.x;
        o.y = acc[r].y + zbv.y - sq.y;
        o.z = acc[r].z + zbv.z - sq.z;
        o.w = acc[r].w + zbv.w - sq.w;
        if (mn == 0) { o.x=o.y=o.z=o.w=-1e30f; }
        else {
            if (mm.x == 0) o.x = -1e30f;
            if (mm.y == 0) o.y = -1e30f;
            if (mm.z == 0) o.z = -1e30f;
            if (mm.w == 0) o.w = -1e30f;
        }
        *(float4*)(g_att + (size_t)h*NN*NN + (size_t)row*NN + m0 + tx*4) = o;
    }
}

// =================== softmax: one block per n, warp per head ==========
__global__ void softmax_kernel() {
    int n = blockIdx.x;
    int w = threadIdx.x >> 5, lane = threadIdx.x & 31;   // 384 threads
    float* row = g_att + ((size_t)w*NN + (size_t)n)*NN;
    float4* row4 = (float4*)row;

    float4 v[4];
    #pragma unroll
    for (int i = 0; i < 4; i++) v[i] = row4[lane + 32*i];

    float mx = -1e30f;
    #pragma unroll
    for (int i = 0; i < 4; i++)
        mx = fmaxf(mx, fmaxf(fmaxf(v[i].x, v[i].y), fmaxf(v[i].z, v[i].w)));
    #pragma unroll
    for (int o = 16; o; o >>= 1) mx = fmaxf(mx, __shfl_xor_sync(0xffffffffu, mx, o));

    float s = 0.f;
    #pragma unroll
    for (int i = 0; i < 4; i++) {
        v[i].x = __expf(v[i].x - mx); v[i].y = __expf(v[i].y - mx);
        v[i].z = __expf(v[i].z - mx); v[i].w = __expf(v[i].w - mx);
        s += v[i].x + v[i].y + v[i].z + v[i].w;
    }
    #pragma unroll
    for (int o = 16; o; o >>= 1) s += __shfl_xor_sync(0xffffffffu, s, o);
    float inv = 1.f / s;
    #pragma unroll
    for (int i = 0; i < 4; i++) {
        v[i].x *= inv; v[i].y *= inv; v[i].z *= inv; v[i].w *= inv;
        row4[lane + 32*i] = v[i];
    }
}

// =================== wsum: pair + v/vpg in one block per n ============
// 384 threads: warps 0-7 (256t) pair over z; warps 8-11 (120t) v40 sums.
__global__ void attn_wsum_kernel(const float* __restrict__ z,
                                 const float* __restrict__ trans,
                                 const float* __restrict__ rot) {
    __shared__ __align__(16) float w_s[NN*HH];     // [m][h], 24 KB
    __shared__ float acc_s[HH*168];
    __shared__ float R[9], T[3];

    int n = blockIdx.x, tid = threadIdx.x;   // 384
    #pragma unroll
    for (int h = 0; h < HH; h++) {
        const float* src = g_att + ((size_t)h*NN + (size_t)n)*NN;
        for (int i = tid; i < NN; i += 384) w_s[i*HH + h] = src[i];
    }
    for (int i = tid; i < HH*168; i += 384) acc_s[i] = 0.f;
    if (tid < 9) R[tid] = rot[n*9 + tid];
    if (tid < 3) T[tid] = trans[n*3 + tid];
    __syncthreads();

    if (tid < 256) {
        // ---- pair features: out[h, c] = sum_m w[m,h]*z[n,m,c] ----
        int c_g    = tid & 31;
        int stripe = tid >> 5;
        float4 acc[HH];
        #pragma unroll
        for (int h = 0; h < HH; h++) acc[h] = make_float4(0.f,0.f,0.f,0.f);

        const float4* zrow = (const float4*)(z + (size_t)n*NN*CZ);
        int mbeg = stripe*64;
        #pragma unroll 4
        for (int it = 0; it < 64; it++) {
            int m = mbeg + it;
            float4 zv = __ldg(zrow + m*32 + c_g);
            const float4* wr = (const float4*)(w_s + m*HH);
            float4 w0 = wr[0], w1 = wr[1], w2 = wr[2];
            const float* wf = (const float*)&w0;
            #pragma unroll
            for (int h = 0; h < 4; h++) {
                float wv = wf[h];
                acc[h].x += wv*zv.x; acc[h].y += wv*zv.y;
                acc[h].z += wv*zv.z; acc[h].w += wv*zv.w;
            }
            const float* wf1 = (const float*)&w1;
            #pragma unroll
            for (int h = 0; h < 4; h++) {
                float wv = wf1[h];
                acc[4+h].x += wv*zv.x; acc[4+h].y += wv*zv.y;
                acc[4+h].z += wv*zv.z; acc[4+h].w += wv*zv.w;
            }
            const float* wf2 = (const float*)&w2;
            #pragma unroll
            for (int h = 0; h < 4; h++) {
                float wv = wf2[h];
                acc[8+h].x += wv*zv.x; acc[8+h].y += wv*zv.y;
                acc[8+h].z += wv*zv.z; acc[8+h].w += wv*zv.w;
            }
        }
        #pragma unroll
        for (int h = 0; h < HH; h++) {
            float* dst = acc_s + h*168 + 40 + c_g*4;
            atomicAdd(dst+0, acc[h].x);
            atomicAdd(dst+1, acc[h].y);
            atomicAdd(dst+2, acc[h].z);
            atomicAdd(dst+3, acc[h].w);
        }
    } else {
        // ---- v+vpg from packed v40: thread = (h, col-quad), coalesced rows
        int vt = tid - 256;   // 0..127, use 0..119
        if (vt < 120) {
            int h = vt / 10, q = vt % 10;       // q*4 covers 0..39
            const float* src = g_v40 + (size_t)h*NN*40 + q*4;
            const float* wcol = w_s + h;
            float4 a = make_float4(0.f,0.f,0.f,0.f);
            #pragma unroll 4
            for (int m = 0; m < NN; m++) {
                float4 xv = __ldg((const float4*)(src + (size_t)m*40));
                float wv = wcol[m*HH];
                a.x += wv*xv.x; a.y += wv*xv.y; a.z += wv*xv.z; a.w += wv*xv.w;
            }
            *(float4*)(acc_s + h*168 + q*4) = a;
        }
    }
    __syncthreads();

    // ---- finalize ----
    for (int s_ = tid; s_ < HH*168; s_ += 384) {
        int h = s_/168, j = s_%168;
        float val = acc_s[s_];
        if (j < 16)       g_feat[(size_t)n*FEAT + h*FH + j] = val;
        else if (j >= 40) g_feat[(size_t)n*FEAT + h*FH + 48 + (j-40)] = val;
    }
    if (tid < HH*PVN) {
        int h = tid / PVN, p = tid % PVN;
        const float* vo = acc_s + h*168 + 16 + p*3;
        float x0_ = vo[0] - T[0];
        float x1_ = vo[1] - T[1];
        float x2_ = vo[2] - T[2];
        float l0 = R[0]*x0_ + R[3]*x1_ + R[6]*x2_;
        float l1 = R[1]*x0_ + R[4]*x1_ + R[7]*x2_;
        float l2 = R[2]*x0_ + R[5]*x1_ + R[8]*x2_;
        g_feat[(size_t)n*FEAT + h*FH + 16 + p*3 + 0] = l0;
        g_feat[(size_t)n*FEAT + h*FH + 16 + p*3 + 1] = l1;
        g_feat[(size_t)n*FEAT + h*FH + 16 + p*3 + 2] = l2;
        g_feat[(size_t)n*FEAT + h*FH + 40 + p] = sqrtf(l0*l0 + l1*l1 + l2*l2);
    }
}

// =================== output projection: split-K, 8x4 micro ============
#define OT_M 128
#define OT_N 64
#define OT_K 16
#define KSPLIT (FEAT/SPLITS)   // 352
__global__ void out_gemm_kernel(const float* __restrict__ wo) {
    int n0   = blockIdx.x*OT_M;
    int col0 = blockIdx.y*OT_N;
    int sp   = blockIdx.z;
    __shared__ float sA[OT_K][OT_M];
    __shared__ float sB[OT_K][OT_N];
    int tid = threadIdx.x;   // 256
    int tx = tid & 15, ty = tid >> 4;
    float4 acc[8] = {};
    int kbeg = sp*KSPLIT, kend = kbeg + KSPLIT;
    for (int k0 = kbeg; k0 < kend; k0 += OT_K) {
        for (int i = tid; i < OT_M*OT_K/4; i += 256) {
            int m = i >> 2, k4 = (i & 3) * 4;
            float4 v = *(const float4*)(g_feat + (size_t)(n0+m)*FEAT + k0 + k4);
            sA[k4+0][m]=v.x; sA[k4+1][m]=v.y; sA[k4+2][m]=v.z; sA[k4+3][m]=v.w;
        }
        {
            int k = tid >> 4, c4 = (tid & 15) * 4;
            *(float4*)&sB[k][c4] = *(const float4*)(wo + (size_t)(k0+k)*COUT + col0 + c4);
        }
        __syncthreads();
        #pragma unroll
        for (int kk = 0; kk < OT_K; kk++) {
            float4 b  = *(float4*)&sB[kk][tx*4];
            float4 a0 = *(float4*)&sA[kk][ty*8];
            float4 a1 = *(float4*)&sA[kk][ty*8+4];
            const float* af0 = (const float*)&a0;
            const float* af1 = (const float*)&a1;
            #pragma unroll
            for (int r = 0; r < 4; r++) {
                float av = af0[r];
                acc[r].x += av*b.x; acc[r].y += av*b.y; acc[r].z += av*b.z; acc[r].w += av*b.w;
            }
            #pragma unroll
            for (int r = 0; r < 4; r++) {
                float av = af1[r];
                acc[4+r].x += av*b.x; acc[4+r].y += av*b.y; acc[4+r].z += av*b.z; acc[4+r].w += av*b.w;
            }
        }
        __syncthreads();
    }
    #pragma unroll
    for (int r = 0; r < 8; r++)
        *(float4*)&g_opart[sp][n0+ty*8+r][col0+tx*4] = acc[r];
}

__global__ void out_reduce_kernel(const float* __restrict__ bo,
                                  float* __restrict__ out) {
    int n = blockIdx.x, o = threadIdx.x;
    float a = bo[o];
    #pragma unroll
    for (int sp = 0; sp < SPLITS; sp++) a += g_opart[sp][n][o];
    out[(size_t)n*COUT + o] = a;
}

// ---------------- launch ---------------------------------------------------
extern "C" void kernel_launch(void* const* d_in, const int* in_sizes, int n_in,
                              void* d_out, int out_size) {
    const float* s     = (const float*)d_in[0];
    const float* z     = (const float*)d_in[1];
    const float* trans = (const float*)d_in[2];
    const float* rot   = (const float*)d_in[3];
    const int*   mask  = (const int*)  d_in[4];
    const float* wq    = (const float*)d_in[5];
    const float* bq    = (const float*)d_in[6];
    const float* wk    = (const float*)d_in[7];
    const float* bk    = (const float*)d_in[8];
    const float* wv    = (const float*)d_in[9];
    const float* bv    = (const float*)d_in[10];
    const float* wqp   = (const float*)d_in[11];
    const float* bqp   = (const float*)d_in[12];
    const float* wkp   = (const float*)d_in[13];
    const float* bkp   = (const float*)d_in[14];
    const float* wvp   = (const float*)d_in[15];
    const float* bvp   = (const float*)d_in[16];
    const float* wb    = (const float*)d_in[17];
    const float* bb    = (const float*)d_in[18];
    const float* wo    = (const float*)d_in[19];
    const float* bo    = (const float*)d_in[20];
    float* out = (float*)d_out;
    (void)bb;  // bb cancels in softmax

    zb_gemm_kernel<<<NN, 128>>>(z, wb);
    proj_gemm_kernel<<<dim3(NN/PT_M, 24), 192>>>(s,
        wq, bq, wk, bk, wv, bv, wqp, bqp, wkp, bkp, wvp, bvp);
    prep_kernel<<<NN, 192>>>(rot, trans);
    logits_gemm_kernel<<<dim3(8, 8, HH), 256>>>(mask);
    softmax_kernel<<<NN, 384>>>();
    attn_wsum_kernel<<<NN, 384>>>(z, trans, rot);
    out_gemm_kernel<<<dim3(NN/OT_M, COUT/OT_N, SPLITS), 256>>>(wo);
    out_reduce_kernel<<<NN, COUT>>>(bo, out);
}

// round 17
// speedup vs baseline: 1.3699x; 1.3699x over previous
#include <cuda_runtime.h>
#include <math.h>

// Problem constants
#define NN    512
#define CS    384
#define CZ    128
#define HH    12
#define CH    16
#define PQN   4
#define PVN   8
#define DPROJ 1152
#define FH    (CH + PVN*3 + PVN + CZ)  // 176
#define FEAT  (HH*FH)                  // 2112
#define COUT  384
#define DK    28                       // combined qk+point dim

// segment bases inside g_proj row
#define OFF_PQ_Q   0
#define OFF_PQ_K   192
#define OFF_PQ_V   384
#define OFF_PQ_QP  576
#define OFF_PQ_KP  720
#define OFF_PQ_VP  864

// ---------------- scratch ----------------
__device__ __align__(16) float g_proj[NN*DPROJ];
__device__ __align__(16) float g_qk  [HH*NN*DK];            // Q' = [0.25*q, qpg]
__device__ __align__(16) float g_kk  [HH*NN*DK];            // K' = [k, kpg]
__device__ __align__(16) float g_sqk [HH*NN];               // 0.5*|kpg|^2
__device__ __align__(16) float g_v40 [(size_t)HH*NN*40];    // [h][n][v(16)|vpg(24)]
__device__ __align__(16) float g_feat[NN*FEAT];
__device__ __align__(16) float g_zb  [(size_t)HH*NN*NN];    // [h][n][m]
__device__ __align__(16) float g_att [(size_t)HH*NN*NN];    // logits -> weights
#define SPLITS 6
__device__ __align__(16) float g_opart[SPLITS][NN][COUT];

// =================== fused projection SGEMM ===========================
#define PT_M 64
#define PT_N 48
#define PT_K 16
__global__ void proj_gemm_kernel(const float* __restrict__ s,
    const float* __restrict__ wq,  const float* __restrict__ bq,
    const float* __restrict__ wk,  const float* __restrict__ bk,
    const float* __restrict__ wv,  const float* __restrict__ bv,
    const float* __restrict__ wqp, const float* __restrict__ bqp,
    const float* __restrict__ wkp, const float* __restrict__ bkp,
    const float* __restrict__ wvp, const float* __restrict__ bvp) {
    int bt = blockIdx.y;
    const float *W, *B; int Dout, base, t;
    if      (bt < 4)  { W=wq;  B=bq;  Dout=192; base=OFF_PQ_Q;  t=bt; }
    else if (bt < 8)  { W=wk;  B=bk;  Dout=192; base=OFF_PQ_K;  t=bt-4; }
    else if (bt < 12) { W=wv;  B=bv;  Dout=192; base=OFF_PQ_V;  t=bt-8; }
    else if (bt < 15) { W=wqp; B=bqp; Dout=144; base=OFF_PQ_QP; t=bt-12; }
    else if (bt < 18) { W=wkp; B=bkp; Dout=144; base=OFF_PQ_KP; t=bt-15; }
    else              { W=wvp; B=bvp; Dout=288; base=OFF_PQ_VP; t=bt-18; }
    int col0 = t*PT_N;
    int n0   = blockIdx.x*PT_M;

    __shared__ float sA[PT_K][PT_M];
    __shared__ float sB[PT_K][PT_N];
    int tid = threadIdx.x;           // 192
    int tx = tid % 12, ty = tid / 12;
    float4 acc[4] = {};

    for (int k0 = 0; k0 < CS; k0 += PT_K) {
        for (int i = tid; i < PT_M*PT_K/4; i += 192) {
            int m = i >> 2, k4 = (i & 3) * 4;
            float4 v = *(const float4*)(s + (size_t)(n0+m)*CS + k0 + k4);
            sA[k4+0][m]=v.x; sA[k4+1][m]=v.y; sA[k4+2][m]=v.z; sA[k4+3][m]=v.w;
        }
        for (int i = tid; i < PT_K*PT_N/4; i += 192) {
            int k = i / 12, c4 = (i % 12) * 4;
            *(float4*)&sB[k][c4] = *(const float4*)(W + (size_t)(k0+k)*Dout + col0 + c4);
        }
        __syncthreads();
        #pragma unroll
        for (int kk = 0; kk < PT_K; kk++) {
            float4 b = *(float4*)&sB[kk][tx*4];
            float4 a = *(float4*)&sA[kk][ty*4];
            acc[0].x += a.x*b.x; acc[0].y += a.x*b.y; acc[0].z += a.x*b.z; acc[0].w += a.x*b.w;
            acc[1].x += a.y*b.x; acc[1].y += a.y*b.y; acc[1].z += a.y*b.z; acc[1].w += a.y*b.w;
            acc[2].x += a.z*b.x; acc[2].y += a.z*b.y; acc[2].z += a.z*b.z; acc[2].w += a.z*b.w;
            acc[3].x += a.w*b.x; acc[3].y += a.w*b.y; acc[3].z += a.w*b.z; acc[3].w += a.w*b.w;
        }
        __syncthreads();
    }
    float4 bias4 = *(const float4*)(B + col0 + tx*4);
    #pragma unroll
    for (int r = 0; r < 4; r++) {
        float4 o = acc[r];
        o.x += bias4.x; o.y += bias4.y; o.z += bias4.z; o.w += bias4.w;
        *(float4*)(g_proj + (size_t)(n0+ty*4+r)*DPROJ + base + col0 + tx*4) = o;
    }
}

// =================== prep: rotate points, build Q'/K'/sqk/v40 =========
__global__ void prep_kernel(const float* __restrict__ rot,
                            const float* __restrict__ trans) {
    int n = blockIdx.x, t = threadIdx.x;   // 192 threads
    __shared__ float R[9], T[3];
    __shared__ float kpg_s[144];
    if (t < 9) R[t] = rot[n*9 + t];
    if (t < 3) T[t] = trans[n*3 + t];
    __syncthreads();

    {
        int h = t / 16, c = t % 16;
        g_qk[(size_t)h*NN*DK + n*DK + c] = g_proj[(size_t)n*DPROJ + t] * 0.25f;
        g_kk[(size_t)h*NN*DK + n*DK + c] = g_proj[(size_t)n*DPROJ + 192 + t];
        g_v40[(size_t)h*NN*40 + (size_t)n*40 + c] =
            g_proj[(size_t)n*DPROJ + OFF_PQ_V + t];
    }
    if (t < 48) {               // qp
        const float* l = g_proj + (size_t)n*DPROJ + OFF_PQ_QP + t*3;
        float l0=l[0], l1=l[1], l2=l[2];
        int h = t/4, p = t%4;
        float* dst = g_qk + (size_t)h*NN*DK + n*DK + 16 + p*3;
        dst[0] = R[0]*l0 + R[1]*l1 + R[2]*l2 + T[0];
        dst[1] = R[3]*l0 + R[4]*l1 + R[5]*l2 + T[1];
        dst[2] = R[6]*l0 + R[7]*l1 + R[8]*l2 + T[2];
    } else if (t < 96) {        // kp
        int tt = t - 48;
        const float* l = g_proj + (size_t)n*DPROJ + OFF_PQ_KP + tt*3;
        float l0=l[0], l1=l[1], l2=l[2];
        int h = tt/4, p = tt%4;
        float g0 = R[0]*l0 + R[1]*l1 + R[2]*l2 + T[0];
        float g1 = R[3]*l0 + R[4]*l1 + R[5]*l2 + T[1];
        float g2 = R[6]*l0 + R[7]*l1 + R[8]*l2 + T[2];
        float* dst = g_kk + (size_t)h*NN*DK + n*DK + 16 + p*3;
        dst[0]=g0; dst[1]=g1; dst[2]=g2;
        kpg_s[tt*3+0]=g0; kpg_s[tt*3+1]=g1; kpg_s[tt*3+2]=g2;
    } else {                    // vp -> packed into v40 cols 16..39
        int tt = t - 96;        // 0..95 = h*8+p
        const float* l = g_proj + (size_t)n*DPROJ + OFF_PQ_VP + tt*3;
        float l0=l[0], l1=l[1], l2=l[2];
        int h = tt/8, p = tt%8;
        float* dst = g_v40 + (size_t)h*NN*40 + (size_t)n*40 + 16 + p*3;
        dst[0] = R[0]*l0 + R[1]*l1 + R[2]*l2 + T[0];
        dst[1] = R[3]*l0 + R[4]*l1 + R[5]*l2 + T[1];
        dst[2] = R[6]*l0 + R[7]*l1 + R[8]*l2 + T[2];
    }
    __syncthreads();
    if (t < HH) {
        float s = 0.f;
        #pragma unroll
        for (int j = 0; j < 12; j++) { float v = kpg_s[t*12 + j]; s += v*v; }
        g_sqk[t*NN + n] = 0.5f * s;
    }
}

// =================== zb GEMM v2: transposed stage, float4 wb ==========
// zb[h][n][m] = z[n,m,:]@wb[:,h];  grid (NN, 2), 128 thr, 256 m per block
#define ZKC 16
#define ZB_MH 256
__global__ void zb_gemm_kernel(const float* __restrict__ z,
                               const float* __restrict__ wb) {
    __shared__ float z_s[ZKC][ZB_MH];          // 16 KB, [k][row]
    __shared__ __align__(16) float wb_s[CZ*HH]; // 6 KB, [k][h]
    int n = blockIdx.x, mh = blockIdx.y, tid = threadIdx.x;   // 128
    int m0 = mh*ZB_MH;
    for (int i = tid; i < CZ*HH; i += 128) wb_s[i] = wb[i];

    float acc[2][HH] = {};
    const float* zbase = z + ((size_t)n*NN + m0)*CZ;

    for (int c = 0; c < CZ/ZKC; c++) {
        __syncthreads();
        // stage 256 rows x 16 k, transposed to [k][row]
        for (int i = tid; i < ZB_MH*4; i += 128) {
            int row = i >> 2, c4 = (i & 3) * 4;
            float4 v = *(const float4*)(zbase + (size_t)row*CZ + c*ZKC + c4);
            z_s[c4+0][row]=v.x; z_s[c4+1][row]=v.y;
            z_s[c4+2][row]=v.z; z_s[c4+3][row]=v.w;
        }
        __syncthreads();
        #pragma unroll
        for (int k = 0; k < ZKC; k++) {
            float z0 = z_s[k][tid];
            float z1 = z_s[k][tid + 128];
            const float* wr = wb_s + (c*ZKC + k)*HH;
            float4 w0 = *(const float4*)(wr);
            float4 w1 = *(const float4*)(wr+4);
            float4 w2 = *(const float4*)(wr+8);
            acc[0][0] += z0*w0.x;  acc[1][0] += z1*w0.x;
            acc[0][1] += z0*w0.y;  acc[1][1] += z1*w0.y;
            acc[0][2] += z0*w0.z;  acc[1][2] += z1*w0.z;
            acc[0][3] += z0*w0.w;  acc[1][3] += z1*w0.w;
            acc[0][4] += z0*w1.x;  acc[1][4] += z1*w1.x;
            acc[0][5] += z0*w1.y;  acc[1][5] += z1*w1.y;
            acc[0][6] += z0*w1.z;  acc[1][6] += z1*w1.z;
            acc[0][7] += z0*w1.w;  acc[1][7] += z1*w1.w;
            acc[0][8] += z0*w2.x;  acc[1][8] += z1*w2.x;
            acc[0][9] += z0*w2.y;  acc[1][9] += z1*w2.y;
            acc[0][10]+= z0*w2.z;  acc[1][10]+= z1*w2.z;
            acc[0][11]+= z0*w2.w;  acc[1][11]+= z1*w2.w;
        }
    }
    #pragma unroll
    for (int h = 0; h < HH; h++) {
        float* dst = g_zb + (size_t)h*NN*NN + (size_t)n*NN + m0;
        dst[tid]       = acc[0][h];
        dst[tid + 128] = acc[1][h];
    }
}

// =================== logits GEMM: per-head 64x64x28 + epilogue ========
__global__ void logits_gemm_kernel(const int* __restrict__ mask) {
    int m0 = blockIdx.x*64, n0 = blockIdx.y*64, h = blockIdx.z;
    __shared__ float Qs[DK][64];
    __shared__ float Ks[DK][64];
    int tid = threadIdx.x;   // 256
    int tx = tid & 15, ty = tid >> 4;

    const float4* qsrc = (const float4*)(g_qk + (size_t)h*NN*DK + (size_t)n0*DK);
    const float4* ksrc = (const float4*)(g_kk + (size_t)h*NN*DK + (size_t)m0*DK);
    for (int i = tid; i < 64*7; i += 256) {
        int row = i / 7, q = i % 7;
        float4 v = qsrc[row*7 + q];
        Qs[q*4+0][row]=v.x; Qs[q*4+1][row]=v.y; Qs[q*4+2][row]=v.z; Qs[q*4+3][row]=v.w;
        float4 w = ksrc[row*7 + q];
        Ks[q*4+0][row]=w.x; Ks[q*4+1][row]=w.y; Ks[q*4+2][row]=w.z; Ks[q*4+3][row]=w.w;
    }
    __syncthreads();

    float4 acc[4] = {};
    #pragma unroll
    for (int k = 0; k < DK; k++) {
        float4 b = *(float4*)&Ks[k][tx*4];
        float4 a = *(float4*)&Qs[k][ty*4];
        acc[0].x += a.x*b.x; acc[0].y += a.x*b.y; acc[0].z += a.x*b.z; acc[0].w += a.x*b.w;
        acc[1].x += a.y*b.x; acc[1].y += a.y*b.y; acc[1].z += a.y*b.z; acc[1].w += a.y*b.w;
        acc[2].x += a.z*b.x; acc[2].y += a.z*b.y; acc[2].z += a.z*b.z; acc[2].w += a.z*b.w;
        acc[3].x += a.w*b.x; acc[3].y += a.w*b.y; acc[3].z += a.w*b.z; acc[3].w += a.w*b.w;
    }

    float4 sq = *(const float4*)(g_sqk + h*NN + m0 + tx*4);
    int4 mm = *(const int4*)(mask + m0 + tx*4);
    #pragma unroll
    for (int r = 0; r < 4; r++) {
        int row = n0 + ty*4 + r;
        int mn = __ldg(mask + row);
        float4 zbv = *(const float4*)(g_zb + (size_t)h*NN*NN + (size_t)row*NN + m0 + tx*4);
        float4 o;
        o.x = acc[r].x + zbv.x - sq.x;
        o.y = acc[r].y + zbv.y - sq.y;
        o.z = acc[r].z + zbv.z - sq.z;
        o.w = acc[r].w + zbv.w - sq.w;
        if (mn == 0) { o.x=o.y=o.z=o.w=-1e30f; }
        else {
            if (mm.x == 0) o.x = -1e30f;
            if (mm.y == 0) o.y = -1e30f;
            if (mm.z == 0) o.z = -1e30f;
            if (mm.w == 0) o.w = -1e30f;
        }
        *(float4*)(g_att + (size_t)h*NN*NN + (size_t)row*NN + m0 + tx*4) = o;
    }
}

// =================== softmax: one block per n, warp per head ==========
__global__ void softmax_kernel() {
    int n = blockIdx.x;
    int w = threadIdx.x >> 5, lane = threadIdx.x & 31;   // 384 threads
    float* row = g_att + ((size_t)w*NN + (size_t)n)*NN;
    float4* row4 = (float4*)row;

    float4 v[4];
    #pragma unroll
    for (int i = 0; i < 4; i++) v[i] = row4[lane + 32*i];

    float mx = -1e30f;
    #pragma unroll
    for (int i = 0; i < 4; i++)
        mx = fmaxf(mx, fmaxf(fmaxf(v[i].x, v[i].y), fmaxf(v[i].z, v[i].w)));
    #pragma unroll
    for (int o = 16; o; o >>= 1) mx = fmaxf(mx, __shfl_xor_sync(0xffffffffu, mx, o));

    float s = 0.f;
    #pragma unroll
    for (int i = 0; i < 4; i++) {
        v[i].x = __expf(v[i].x - mx); v[i].y = __expf(v[i].y - mx);
        v[i].z = __expf(v[i].z - mx); v[i].w = __expf(v[i].w - mx);
        s += v[i].x + v[i].y + v[i].z + v[i].w;
    }
    #pragma unroll
    for (int o = 16; o; o >>= 1) s += __shfl_xor_sync(0xffffffffu, s, o);
    float inv = 1.f / s;
    #pragma unroll
    for (int i = 0; i < 4; i++) {
        v[i].x *= inv; v[i].y *= inv; v[i].z *= inv; v[i].w *= inv;
        row4[lane + 32*i] = v[i];
    }
}

// =================== wsum: pair + v/vpg in one block per n ============
__global__ void attn_wsum_kernel(const float* __restrict__ z,
                                 const float* __restrict__ trans,
                                 const float* __restrict__ rot) {
    __shared__ __align__(16) float w_s[NN*HH];     // [m][h], 24 KB
    __shared__ float acc_s[HH*168];
    __shared__ float R[9], T[3];

    int n = blockIdx.x, tid = threadIdx.x;   // 384
    #pragma unroll
    for (int h = 0; h < HH; h++) {
        const float* src = g_att + ((size_t)h*NN + (size_t)n)*NN;
        for (int i = tid; i < NN; i += 384) w_s[i*HH + h] = src[i];
    }
    for (int i = tid; i < HH*168; i += 384) acc_s[i] = 0.f;
    if (tid < 9) R[tid] = rot[n*9 + tid];
    if (tid < 3) T[tid] = trans[n*3 + tid];
    __syncthreads();

    if (tid < 256) {
        int c_g    = tid & 31;
        int stripe = tid >> 5;
        float4 acc[HH];
        #pragma unroll
        for (int h = 0; h < HH; h++) acc[h] = make_float4(0.f,0.f,0.f,0.f);

        const float4* zrow = (const float4*)(z + (size_t)n*NN*CZ);
        int mbeg = stripe*64;
        #pragma unroll 4
        for (int it = 0; it < 64; it++) {
            int m = mbeg + it;
            float4 zv = __ldg(zrow + m*32 + c_g);
            const float4* wr = (const float4*)(w_s + m*HH);
            float4 w0 = wr[0], w1 = wr[1], w2 = wr[2];
            const float* wf = (const float*)&w0;
            #pragma unroll
            for (int h = 0; h < 4; h++) {
                float wv = wf[h];
                acc[h].x += wv*zv.x; acc[h].y += wv*zv.y;
                acc[h].z += wv*zv.z; acc[h].w += wv*zv.w;
            }
            const float* wf1 = (const float*)&w1;
            #pragma unroll
            for (int h = 0; h < 4; h++) {
                float wv = wf1[h];
                acc[4+h].x += wv*zv.x; acc[4+h].y += wv*zv.y;
                acc[4+h].z += wv*zv.z; acc[4+h].w += wv*zv.w;
            }
            const float* wf2 = (const float*)&w2;
            #pragma unroll
            for (int h = 0; h < 4; h++) {
                float wv = wf2[h];
                acc[8+h].x += wv*zv.x; acc[8+h].y += wv*zv.y;
                acc[8+h].z += wv*zv.z; acc[8+h].w += wv*zv.w;
            }
        }
        #pragma unroll
        for (int h = 0; h < HH; h++) {
            float* dst = acc_s + h*168 + 40 + c_g*4;
            atomicAdd(dst+0, acc[h].x);
            atomicAdd(dst+1, acc[h].y);
            atomicAdd(dst+2, acc[h].z);
            atomicAdd(dst+3, acc[h].w);
        }
    } else {
        int vt = tid - 256;   // 0..127, use 0..119
        if (vt < 120) {
            int h = vt / 10, q = vt % 10;
            const float* src = g_v40 + (size_t)h*NN*40 + q*4;
            const float* wcol = w_s + h;
            float4 a = make_float4(0.f,0.f,0.f,0.f);
            #pragma unroll 4
            for (int m = 0; m < NN; m++) {
                float4 xv = __ldg((const float4*)(src + (size_t)m*40));
                float wv = wcol[m*HH];
                a.x += wv*xv.x; a.y += wv*xv.y; a.z += wv*xv.z; a.w += wv*xv.w;
            }
            *(float4*)(acc_s + h*168 + q*4) = a;
        }
    }
    __syncthreads();

    for (int s_ = tid; s_ < HH*168; s_ += 384) {
        int h = s_/168, j = s_%168;
        float val = acc_s[s_];
        if (j < 16)       g_feat[(size_t)n*FEAT + h*FH + j] = val;
        else if (j >= 40) g_feat[(size_t)n*FEAT + h*FH + 48 + (j-40)] = val;
    }
    if (tid < HH*PVN) {
        int h = tid / PVN, p = tid % PVN;
        const float* vo = acc_s + h*168 + 16 + p*3;
        float x0_ = vo[0] - T[0];
        float x1_ = vo[1] - T[1];
        float x2_ = vo[2] - T[2];
        float l0 = R[0]*x0_ + R[3]*x1_ + R[6]*x2_;
        float l1 = R[1]*x0_ + R[4]*x1_ + R[7]*x2_;
        float l2 = R[2]*x0_ + R[5]*x1_ + R[8]*x2_;
        g_feat[(size_t)n*FEAT + h*FH + 16 + p*3 + 0] = l0;
        g_feat[(size_t)n*FEAT + h*FH + 16 + p*3 + 1] = l1;
        g_feat[(size_t)n*FEAT + h*FH + 16 + p*3 + 2] = l2;
        g_feat[(size_t)n*FEAT + h*FH + 40 + p] = sqrtf(l0*l0 + l1*l1 + l2*l2);
    }
}

// =================== output projection: split-K, 8x4 micro ============
#define OT_M 128
#define OT_N 64
#define OT_K 16
#define KSPLIT (FEAT/SPLITS)   // 352
__global__ void out_gemm_kernel(const float* __restrict__ wo) {
    int n0   = blockIdx.x*OT_M;
    int col0 = blockIdx.y*OT_N;
    int sp   = blockIdx.z;
    __shared__ float sA[OT_K][OT_M];
    __shared__ float sB[OT_K][OT_N];
    int tid = threadIdx.x;   // 256
    int tx = tid & 15, ty = tid >> 4;
    float4 acc[8] = {};
    int kbeg = sp*KSPLIT, kend = kbeg + KSPLIT;
    for (int k0 = kbeg; k0 < kend; k0 += OT_K) {
        for (int i = tid; i < OT_M*OT_K/4; i += 256) {
            int m = i >> 2, k4 = (i & 3) * 4;
            float4 v = *(const float4*)(g_feat + (size_t)(n0+m)*FEAT + k0 + k4);
            sA[k4+0][m]=v.x; sA[k4+1][m]=v.y; sA[k4+2][m]=v.z; sA[k4+3][m]=v.w;
        }
        {
            int k = tid >> 4, c4 = (tid & 15) * 4;
            *(float4*)&sB[k][c4] = *(const float4*)(wo + (size_t)(k0+k)*COUT + col0 + c4);
        }
        __syncthreads();
        #pragma unroll
        for (int kk = 0; kk < OT_K; kk++) {
            float4 b  = *(float4*)&sB[kk][tx*4];
            float4 a0 = *(float4*)&sA[kk][ty*8];
            float4 a1 = *(float4*)&sA[kk][ty*8+4];
            const float* af0 = (const float*)&a0;
            const float* af1 = (const float*)&a1;
            #pragma unroll
            for (int r = 0; r < 4; r++) {
                float av = af0[r];
                acc[r].x += av*b.x; acc[r].y += av*b.y; acc[r].z += av*b.z; acc[r].w += av*b.w;
            }
            #pragma unroll
            for (int r = 0; r < 4; r++) {
                float av = af1[r];
                acc[4+r].x += av*b.x; acc[4+r].y += av*b.y; acc[4+r].z += av*b.z; acc[4+r].w += av*b.w;
            }
        }
        __syncthreads();
    }
    #pragma unroll
    for (int r = 0; r < 8; r++)
        *(float4*)&g_opart[sp][n0+ty*8+r][col0+tx*4] = acc[r];
}

__global__ void out_reduce_kernel(const float* __restrict__ bo,
                                  float* __restrict__ out) {
    int n = blockIdx.x, o = threadIdx.x;
    float a = bo[o];
    #pragma unroll
    for (int sp = 0; sp < SPLITS; sp++) a += g_opart[sp][n][o];
    out[(size_t)n*COUT + o] = a;
}

// ---------------- launch ---------------------------------------------------
extern "C" void kernel_launch(void* const* d_in, const int* in_sizes, int n_in,
                              void* d_out, int out_size) {
    const float* s     = (const float*)d_in[0];
    const float* z     = (const float*)d_in[1];
    const float* trans = (const float*)d_in[2];
    const float* rot   = (const float*)d_in[3];
    const int*   mask  = (const int*)  d_in[4];
    const float* wq    = (const float*)d_in[5];
    const float* bq    = (const float*)d_in[6];
    const float* wk    = (const float*)d_in[7];
    const float* bk    = (const float*)d_in[8];
    const float* wv    = (const float*)d_in[9];
    const float* bv    = (const float*)d_in[10];
    const float* wqp   = (const float*)d_in[11];
    const float* bqp   = (const float*)d_in[12];
    const float* wkp   = (const float*)d_in[13];
    const float* bkp   = (const float*)d_in[14];
    const float* wvp   = (const float*)d_in[15];
    const float* bvp   = (const float*)d_in[16];
    const float* wb    = (const float*)d_in[17];
    const float* bb    = (const float*)d_in[18];
    const float* wo    = (const float*)d_in[19];
    const float* bo    = (const float*)d_in[20];
    float* out = (float*)d_out;
    (void)bb;  // bb cancels in softmax

    zb_gemm_kernel<<<dim3(NN, 2), 128>>>(z, wb);
    proj_gemm_kernel<<<dim3(NN/PT_M, 24), 192>>>(s,
        wq, bq, wk, bk, wv, bv, wqp, bqp, wkp, bkp, wvp, bvp);
    prep_kernel<<<NN, 192>>>(rot, trans);
    logits_gemm_kernel<<<dim3(8, 8, HH), 256>>>(mask);
    softmax_kernel<<<NN, 384>>>();
    attn_wsum_kernel<<<NN, 384>>>(z, trans, rot);
    out_gemm_kernel<<<dim3(NN/OT_M, COUT/OT_N, SPLITS), 256>>>(wo);
    out_reduce_kernel<<<NN, COUT>>>(bo, out);
}